// round 3
// baseline (speedup 1.0000x reference)
#include <cuda_runtime.h>
#include <math.h>

#define BATCH 16
#define LSEQ  720
#define ECH   64
#define NORD  256
#define OUTL  96
#define KDIM  16384           // NORD * MODES * 2
#define TSUM  672             // 96+192+384
#define HSPLIT 16
#define KCHUNK (KDIM/HSPLIT)  // 1024

// ---------------- static device scratch ----------------
__device__ float g_mean[BATCH*ECH];
__device__ float g_std [BATCH*ECH];
__device__ float g_K[3][384][256];            // Krylov kernels K_d = Ad^d Bd
__device__ float g_P[3][2][256*256];          // ping-pong matrix powers Ad^(2^r)
__device__ float g_G[TSUM*KDIM];              // packed G (tau-major), 44 MB
__device__ float g_Wpack[3][KDIM*256];        // packed weights, 50 MB
__device__ float g_Hpart[HSPLIT][TSUM*256];   // split-K partials
__device__ float g_H[TSUM*256];
__device__ float g_M[384*96];
__device__ float g_Msum[96];

__constant__ int c_tile_s[11] = {0,0,1,1,1,2,2,2,2,2,2};
__constant__ int c_tile_r[11] = {0,64,0,64,128,0,64,128,192,256,320};

__device__ __forceinline__ int seg_off(int s){ return s==0?0:(s==1?96:288); }
__device__ __forceinline__ int seg_T  (int s){ return s==0?96:(s==1?192:384); }

// ---------------- 1. per-(b,e) mean / std over L ----------------
__global__ void stats_kernel(const float* __restrict__ x){
    int b = blockIdx.x;
    int t = threadIdx.x;
    int e = t & 63, q = t >> 6;
    float s = 0.f, sq = 0.f;
    for (int l = q; l < LSEQ; l += 4){
        float v = x[((size_t)b*LSEQ + l)*ECH + e];
        s += v; sq += v*v;
    }
    __shared__ float sh[2][4][64];
    sh[0][q][e] = s; sh[1][q][e] = sq;
    __syncthreads();
    if (q == 0){
        float S  = sh[0][0][e]+sh[0][1][e]+sh[0][2][e]+sh[0][3][e];
        float SQ = sh[1][0][e]+sh[1][1][e]+sh[1][2][e]+sh[1][3][e];
        float m = S * (1.f/LSEQ);
        float var = SQ * (1.f/LSEQ) - m*m;
        g_mean[b*ECH+e] = m;
        g_std [b*ECH+e] = sqrtf(var + 1e-5f);
    }
}

// ---------------- 2. repack (wr, -wi) -> Wpack[kdim][o] ----------------
// Wpack[s][(i*64 + 2k + c)*256 + o] = (c==0) ? wr[s,i,o,k] : -wi[s,i,o,k]
__global__ void wpack_kernel(const float* __restrict__ wr, const float* __restrict__ wi){
    int i = blockIdx.x, s = blockIdx.y;
    int t = threadIdx.x;                         // t == o in write phase
    __shared__ float sh[256*33];
    const float* base_r = wr + (size_t)((s*256 + i)*256)*32;
    const float* base_i = wi + (size_t)((s*256 + i)*256)*32;
    float* out = g_Wpack[s] + (size_t)(i*64)*256;
    for (int idx = t; idx < 8192; idx += 256){
        int o = idx >> 5, k = idx & 31;
        sh[o*33 + k] = base_r[idx];
    }
    __syncthreads();
    #pragma unroll
    for (int k = 0; k < 32; k++)
        out[(size_t)(2*k)*256 + t] = sh[t*33 + k];
    __syncthreads();
    for (int idx = t; idx < 8192; idx += 256){
        int o = idx >> 5, k = idx & 31;
        sh[o*33 + k] = base_i[idx];
    }
    __syncthreads();
    #pragma unroll
    for (int k = 0; k < 32; k++)
        out[(size_t)(2*k+1)*256 + t] = -sh[t*33 + k];
}

// ---------------- 3. init P = Ad, K_0 = Bd ----------------
__global__ void init_kernel(const float* __restrict__ A, const float* __restrict__ Bv){
    int idx = blockIdx.x*blockDim.x + threadIdx.x;
    if (idx < 3*65536){
        int s = idx >> 16, r = idx & 65535;
        g_P[s][0][r] = A[idx];
    } else if (idx < 3*65536 + 768){
        int j = idx - 3*65536;
        int s = j >> 8, i = j & 255;
        g_K[s][0][i] = Bv[j];
    }
}

// ---------------- 4. log-doubling round ----------------
// task 0: K[n .. n+m) = K[0..m) @ P^T    (m = min(n, T-n)),  P = Ad^n
// task 1: P_{2n} = P_n @ P_n             (only if 2n < T)
__global__ void round_kernel(int r){
    int s = blockIdx.y;
    int task = blockIdx.z;
    int Ts = seg_T(s);
    int n = 1 << r;
    int rows; const float *Aop, *Bop; float *Cop; bool nt;
    if (task == 0){
        if (n >= Ts) return;
        int m = min(n, Ts - n);
        rows = m;
        Aop = &g_K[s][0][0];
        Bop = g_P[s][r & 1];
        Cop = &g_K[s][n][0];
        nt  = true;
    } else {
        if (2*n >= Ts) return;
        rows = 256;
        Aop = g_P[s][r & 1];
        Bop = Aop;
        Cop = g_P[s][(r+1)&1];
        nt  = false;
    }
    int rt = (rows + 63) >> 6;
    int tile = blockIdx.x;
    int rowt = tile >> 2, colt = tile & 3;
    if (rowt >= rt) return;
    int row0 = rowt*64, col0 = colt*64;
    __shared__ float As[16][68];
    __shared__ float Bs[16][68];
    int t = threadIdx.x;
    int tm4 = (t >> 4) * 4;
    int tn4 = (t & 15) * 4;
    float acc[16];
    #pragma unroll
    for (int q = 0; q < 16; q++) acc[q] = 0.f;
    for (int kc = 0; kc < 256; kc += 16){
        #pragma unroll
        for (int p = 0; p < 4; p++){
            int idx = t + p*256;
            int kk = idx & 15, m = idx >> 4;
            float v = 0.f;
            if (row0 + m < rows) v = Aop[(size_t)(row0+m)*256 + kc + kk];
            As[kk][m] = v;
        }
        #pragma unroll
        for (int p = 0; p < 4; p++){
            int idx = t + p*256;
            int kk = idx & 15, j = idx >> 4;
            Bs[kk][j] = nt ? Bop[(size_t)(col0+j)*256 + kc + kk]
                           : Bop[(size_t)(kc+kk)*256 + col0 + j];
        }
        __syncthreads();
        #pragma unroll
        for (int kk = 0; kk < 16; kk++){
            float4 av = *(const float4*)&As[kk][tm4];
            float4 bv = *(const float4*)&Bs[kk][tn4];
            float a4[4] = {av.x, av.y, av.z, av.w};
            float b4[4] = {bv.x, bv.y, bv.z, bv.w};
            #pragma unroll
            for (int a = 0; a < 4; a++)
                #pragma unroll
                for (int b = 0; b < 4; b++)
                    acc[a*4+b] += a4[a]*b4[b];
        }
        __syncthreads();
    }
    #pragma unroll
    for (int a = 0; a < 4; a++){
        int m = row0 + tm4 + a;
        if (m < rows){
            #pragma unroll
            for (int b = 0; b < 4; b++)
                Cop[(size_t)m*256 + col0 + tn4 + b] = acc[a*4+b];
        }
    }
}

// ---------------- 5. build packed G ----------------
// S_k[tau,i] = sum_{d=0}^{T-1-tau} K_d[i] e^{-i 2pi k d / T}
// G[tau,i,k] = (alpha_k/T) e^{+i 2pi k (95-tau)/T} S_k[tau,i]; alpha_0=1 else 2
__global__ void gbuild_kernel(){
    int s = blockIdx.y;
    int T = seg_T(s), seg = seg_off(s);
    int t = blockIdx.x*256 + threadIdx.x;   // 0..8191
    int i = t >> 5, k = t & 31;
    const float invT = 1.f/(float)T;
    float mag = (k == 0) ? invT : 2.f*invT;
    float Sr = 0.f, Si = 0.f;
    int m0 = (96 - T) % T; if (m0 < 0) m0 += T;
    int p1 = 0;
    int p2 = (int)(((long long)k * (long long)m0) % T);
    const float c2pi = 6.28318530717958647692f;
    float* G = g_G + (size_t)seg*KDIM + i*64 + 2*k;
    for (int d = 0; d < T; d++){
        float Kd = g_K[s][d][i];
        float s1, c1, s2, c2;
        __sincosf(c2pi * (float)p1 * invT, &s1, &c1);
        Sr += Kd * c1; Si -= Kd * s1;
        __sincosf(c2pi * (float)p2 * invT, &s2, &c2);
        int tau = T - 1 - d;
        float* row = G + (size_t)tau*KDIM;
        row[0] = mag*(c2*Sr - s2*Si);
        row[1] = mag*(c2*Si + s2*Sr);
        p1 += k; if (p1 >= T) p1 -= T;
        p2 += k; if (p2 >= T) p2 -= T;
    }
}

// ---------------- 6. H = G @ Wpack (split-K) ----------------
__global__ void hgemm_kernel(){
    int tile  = blockIdx.x;        // 0..43  (11 row-tiles x 4 col-tiles)
    int split = blockIdx.y;        // 0..HSPLIT-1
    int rowt = tile >> 2, colt = tile & 3;
    int s   = c_tile_s[rowt];
    int row0 = c_tile_r[rowt];
    int Ts = seg_T(s), seg = seg_off(s);
    int col0 = colt*64;
    const float* Abase = g_G + (size_t)seg*KDIM;
    const float* Bbase = g_Wpack[s];
    __shared__ float As[16][68];
    __shared__ float Bs[16][68];
    int t = threadIdx.x;
    int tm4 = (t >> 4) * 4;
    int tn4 = (t & 15) * 4;
    float acc[16];
    #pragma unroll
    for (int q = 0; q < 16; q++) acc[q] = 0.f;
    int kc0 = split*KCHUNK, kc1 = kc0 + KCHUNK;
    for (int kc = kc0; kc < kc1; kc += 16){
        #pragma unroll
        for (int p = 0; p < 4; p++){
            int idx = t + p*256;
            int kk = idx & 15, m = idx >> 4;
            float v = 0.f;
            if (row0 + m < Ts) v = Abase[(size_t)(row0+m)*KDIM + kc + kk];
            As[kk][m] = v;
        }
        #pragma unroll
        for (int p = 0; p < 4; p++){
            int idx = t + p*256;
            int kk = idx & 15, j = idx >> 4;
            Bs[kk][j] = Bbase[(size_t)(kc+kk)*256 + col0 + j];
        }
        __syncthreads();
        #pragma unroll
        for (int kk = 0; kk < 16; kk++){
            float4 av = *(const float4*)&As[kk][tm4];
            float4 bv = *(const float4*)&Bs[kk][tn4];
            float a4[4] = {av.x, av.y, av.z, av.w};
            float b4[4] = {bv.x, bv.y, bv.z, bv.w};
            #pragma unroll
            for (int a = 0; a < 4; a++)
                #pragma unroll
                for (int b = 0; b < 4; b++)
                    acc[a*4+b] += a4[a]*b4[b];
        }
        __syncthreads();
    }
    float* out = g_Hpart[split];
    #pragma unroll
    for (int a = 0; a < 4; a++){
        int m = row0 + tm4 + a;
        if (m < Ts){
            #pragma unroll
            for (int b = 0; b < 4; b++)
                out[(size_t)(seg+m)*256 + col0 + tn4 + b] = acc[a*4+b];
        }
    }
}

__global__ void hreduce_kernel(){
    int r = blockIdx.x*256 + threadIdx.x;   // 672*256
    float a = 0.f;
    #pragma unroll
    for (int sp = 0; sp < HSPLIT; sp++) a += g_Hpart[sp][r];
    g_H[r] = a;
}

// ---------------- 7. M[g,u] = sum_s mlp_w[s] * (H_s @ eval_last[s]^T) ----------------
__global__ void mbuild_kernel(const float* __restrict__ ev, const float* __restrict__ mlp_w){
    int g = blockIdx.x;        // 0..383
    int t = threadIdx.x;       // 256
    __shared__ float hrow[3][256];
    __shared__ float wsh[3];
    if (t < 3) wsh[t] = mlp_w[t];
    #pragma unroll
    for (int s = 0; s < 3; s++){
        int Ts = seg_T(s);
        int tau = g - (384 - Ts);
        hrow[s][t] = (tau >= 0) ? g_H[(size_t)(seg_off(s)+tau)*256 + t] : 0.f;
    }
    __syncthreads();
    if (t < 96){
        float acc = 0.f;
        #pragma unroll
        for (int s = 0; s < 3; s++){
            const float* e = ev + ((size_t)s*96 + t)*256;
            float a = 0.f;
            #pragma unroll 8
            for (int o = 0; o < 256; o++) a += hrow[s][o]*e[o];
            acc += wsh[s]*a;
        }
        g_M[g*96 + t] = acc;
    }
}

__global__ void msum_kernel(){
    int u = threadIdx.x;  // 96
    float a = 0.f;
    for (int g = 0; g < 384; g++) a += g_M[g*96 + u];
    g_Msum[u] = a;
}

// ---------------- 8. final: out[b,u,e] ----------------
__global__ void final_kernel(const float* __restrict__ x,
                             const float* __restrict__ mlp_b,
                             float* __restrict__ out){
    int b = blockIdx.x, u = blockIdx.y;
    int e = threadIdx.x;   // 64
    __shared__ float msh[384];
    for (int g = e; g < 384; g += 64) msh[g] = g_M[g*96 + u];
    __syncthreads();
    const float* xp = x + ((size_t)b*LSEQ + 336)*ECH + e;
    float acc = 0.f;
    #pragma unroll 8
    for (int g = 0; g < 384; g++) acc += xp[(size_t)g*ECH] * msh[g];
    float mean = g_mean[b*ECH+e], sd = g_std[b*ECH+e];
    out[((size_t)b*OUTL + u)*ECH + e] = acc + mean*(1.f - g_Msum[u]) + mlp_b[0]*sd;
}

// ---------------- launch ----------------
extern "C" void kernel_launch(void* const* d_in, const int* in_sizes, int n_in,
                              void* d_out, int out_size){
    const float* x     = (const float*)d_in[0];
    const float* wr    = (const float*)d_in[1];
    const float* wi    = (const float*)d_in[2];
    const float* mlp_w = (const float*)d_in[3];
    const float* mlp_b = (const float*)d_in[4];
    const float* A     = (const float*)d_in[5];
    const float* Bv    = (const float*)d_in[6];
    const float* ev    = (const float*)d_in[7];
    float* out = (float*)d_out;

    stats_kernel<<<BATCH, 256>>>(x);
    wpack_kernel<<<dim3(256,3), 256>>>(wr, wi);
    init_kernel<<<(3*65536 + 768 + 255)/256, 256>>>(A, Bv);
    for (int r = 0; r < 9; r++)
        round_kernel<<<dim3(16,3,2), 256>>>(r);
    gbuild_kernel<<<dim3(32,3), 256>>>();
    hgemm_kernel<<<dim3(44, HSPLIT), 256>>>();
    hreduce_kernel<<<TSUM, 256>>>();
    mbuild_kernel<<<384, 256>>>(ev, mlp_w);
    msum_kernel<<<1, 96>>>();
    final_kernel<<<dim3(BATCH, OUTL), 64>>>(x, mlp_b, out);
}

// round 4
// speedup vs baseline: 1.5958x; 1.5958x over previous
#include <cuda_runtime.h>
#include <math.h>

#define BATCH 16
#define LSEQ  720
#define ECH   64
#define OUTL  96
#define NDIM  6144            // (2k+c)*96+u = 64*96

// ---------------- static device scratch ----------------
__device__ float g_mean[BATCH*ECH];
__device__ float g_std [BATCH*ECH];
__device__ float g_K[3][384][256];            // Krylov kernels K_d = Ad^d Bd
__device__ float g_P[3][2][256*256];          // ping-pong powers Ad^(2^r)
__device__ float g_rpart[3][2][4][256*256];   // split-K partials for rounds
__device__ float g_E[3][256*96];              // mlp_w[s]*ev[s]^T  (o,u)
__device__ float g_WE[3][256*NDIM];           // Wc@E  (i, (2k+c)*96+u), mag folded
__device__ float g_C[672*NDIM];               // K@WE  (seg+d, n)
__device__ float g_Mpart[96][384*96];         // per (s,k) chain partials
__device__ float g_M[384*96];
__device__ float g_Msum[96];

__constant__ int c_tile_s[11] = {0,0,1,1,1,2,2,2,2,2,2};
__constant__ int c_tile_r[11] = {0,64,0,64,128,0,64,128,192,256,320};

__device__ __forceinline__ int seg_off(int s){ return s==0?0:(s==1?96:288); }
__device__ __forceinline__ int seg_T  (int s){ return s==0?96:(s==1?192:384); }

// ---------------- 1. per-(b,e) mean / std ----------------
__global__ void stats_kernel(const float* __restrict__ x){
    int b = blockIdx.x;
    int t = threadIdx.x;
    int e = t & 63, q = t >> 6;
    float s = 0.f, sq = 0.f;
    for (int l = q; l < LSEQ; l += 4){
        float v = x[((size_t)b*LSEQ + l)*ECH + e];
        s += v; sq += v*v;
    }
    __shared__ float sh[2][4][64];
    sh[0][q][e] = s; sh[1][q][e] = sq;
    __syncthreads();
    if (q == 0){
        float S  = sh[0][0][e]+sh[0][1][e]+sh[0][2][e]+sh[0][3][e];
        float SQ = sh[1][0][e]+sh[1][1][e]+sh[1][2][e]+sh[1][3][e];
        float m = S * (1.f/LSEQ);
        float var = SQ * (1.f/LSEQ) - m*m;
        g_mean[b*ECH+e] = m;
        g_std [b*ECH+e] = sqrtf(var + 1e-5f);
    }
}

// ---------------- 2. E[s][o][u] = mlp_w[s] * ev[s,u,o] ----------------
__global__ void egen_kernel(const float* __restrict__ ev, const float* __restrict__ mlp_w){
    int s = blockIdx.x;
    int o = threadIdx.x;
    float w = mlp_w[s];
    for (int u = 0; u < 96; u++)
        g_E[s][o*96 + u] = w * ev[((size_t)(s*96+u))*256 + o];
}

// ---------------- 3. init P = Ad, K_0 = Bd ----------------
__global__ void init_kernel(const float* __restrict__ A, const float* __restrict__ Bv){
    int idx = blockIdx.x*blockDim.x + threadIdx.x;
    if (idx < 3*65536){
        int s = idx >> 16, r = idx & 65535;
        g_P[s][0][r] = A[idx];
    } else if (idx < 3*65536 + 768){
        int j = idx - 3*65536;
        int s = j >> 8, i = j & 255;
        g_K[s][0][i] = Bv[j];
    }
}

// ---------------- 4a. log-doubling round GEMM (split-K=4) ----------------
// task 0: K[n..n+m) = K[0..m) @ P^T   (m=min(n,T-n))
// task 1: P_{2n}    = P_n @ P_n
__global__ void rgemm_kernel(int r){
    int s = blockIdx.y;
    int task  = blockIdx.z >> 2;
    int split = blockIdx.z & 3;
    int Ts = seg_T(s);
    int n = 1 << r;
    int rows; const float *Aop, *Bop; bool nt;
    if (task == 0){
        if (n >= Ts) return;
        rows = min(n, Ts - n);
        Aop = &g_K[s][0][0];
        Bop = g_P[s][r & 1];
        nt  = true;
    } else {
        if (2*n >= Ts) return;
        rows = 256;
        Aop = g_P[s][r & 1];
        Bop = Aop;
        nt  = false;
    }
    float* Cop = g_rpart[s][task][split];
    int tile = blockIdx.x;
    int rowt = tile >> 2, colt = tile & 3;
    if (rowt*64 >= rows) return;
    int row0 = rowt*64, col0 = colt*64;
    __shared__ float As[16][68];
    __shared__ float Bs[16][68];
    int t = threadIdx.x;
    int tm4 = (t >> 4) * 4;
    int tn4 = (t & 15) * 4;
    float acc[16];
    #pragma unroll
    for (int q = 0; q < 16; q++) acc[q] = 0.f;
    int k0 = split*64;
    for (int kc = k0; kc < k0+64; kc += 16){
        #pragma unroll
        for (int p = 0; p < 4; p++){
            int idx = t + p*256;
            int kk = idx & 15, m = idx >> 4;
            As[kk][m] = (row0 + m < rows) ? Aop[(size_t)(row0+m)*256 + kc + kk] : 0.f;
        }
        #pragma unroll
        for (int p = 0; p < 4; p++){
            int idx = t + p*256;
            int kk = idx & 15, j = idx >> 4;
            Bs[kk][j] = nt ? Bop[(size_t)(col0+j)*256 + kc + kk]
                           : Bop[(size_t)(kc+kk)*256 + col0 + j];
        }
        __syncthreads();
        #pragma unroll
        for (int kk = 0; kk < 16; kk++){
            float4 av = *(const float4*)&As[kk][tm4];
            float4 bv = *(const float4*)&Bs[kk][tn4];
            float a4[4] = {av.x, av.y, av.z, av.w};
            float b4[4] = {bv.x, bv.y, bv.z, bv.w};
            #pragma unroll
            for (int a = 0; a < 4; a++)
                #pragma unroll
                for (int b = 0; b < 4; b++)
                    acc[a*4+b] += a4[a]*b4[b];
        }
        __syncthreads();
    }
    #pragma unroll
    for (int a = 0; a < 4; a++){
        int m = row0 + tm4 + a;
        if (m < rows){
            #pragma unroll
            for (int b = 0; b < 4; b++)
                Cop[(size_t)m*256 + col0 + tn4 + b] = acc[a*4+b];
        }
    }
}

// ---------------- 4b. round reduce (sum 4 split partials) ----------------
__global__ void rred_kernel(int r){
    int s = blockIdx.y, task = blockIdx.z;
    int Ts = seg_T(s), n = 1 << r;
    int rows; float* dst;
    if (task == 0){
        if (n >= Ts) return;
        rows = min(n, Ts - n);
        dst = &g_K[s][n][0];
    } else {
        if (2*n >= Ts) return;
        rows = 256;
        dst = g_P[s][(r+1)&1];
    }
    int j4 = blockIdx.x*256 + threadIdx.x;   // float4 index
    int row = j4 >> 6;
    if (row >= rows) return;
    const float4* p0 = (const float4*)g_rpart[s][task][0];
    const float4* p1 = (const float4*)g_rpart[s][task][1];
    const float4* p2 = (const float4*)g_rpart[s][task][2];
    const float4* p3 = (const float4*)g_rpart[s][task][3];
    float4 a = p0[j4], b = p1[j4], c = p2[j4], d = p3[j4];
    float4 o;
    o.x = (a.x+b.x)+(c.x+d.x);
    o.y = (a.y+b.y)+(c.y+d.y);
    o.z = (a.z+b.z)+(c.z+d.z);
    o.w = (a.w+b.w)+(c.w+d.w);
    ((float4*)dst)[j4] = o;
}

// ---------------- 5. WE[s][i][(2k+c)*96+u] = mag_k * sum_o w[i,o,k]*E[o,u] ---
// c=0 -> wr, c=1 -> +wi (complex kept). Double-buffered K-loop over o.
__global__ void wegemm_kernel(const float* __restrict__ wr, const float* __restrict__ wi){
    int i = blockIdx.x, s = blockIdx.y;
    int T = seg_T(s);
    __shared__ float As[2][16][68];   // [o'][2k+c]
    __shared__ float Bs[2][16][98];   // [o'][u]
    const float* wrp = wr + ((size_t)(s*256 + i)*256)*32;
    const float* wip = wi + ((size_t)(s*256 + i)*256)*32;
    const float* E = g_E[s];
    int t = threadIdx.x;
    int a = t >> 4, b = t & 15;       // a: kc-group (4 rows), b: u-group (6 cols)
    float acc[24];
    #pragma unroll
    for (int q = 0; q < 24; q++) acc[q] = 0.f;

    // chunk 0 loads
    #pragma unroll
    for (int p = 0; p < 2; p++){
        int idx = t + p*256;
        int o = idx >> 5, k = idx & 31;
        As[0][o][2*k]   = wrp[o*32 + k];
        As[0][o][2*k+1] = wip[o*32 + k];
    }
    #pragma unroll
    for (int p = 0; p < 6; p++){
        int idx = t + p*256;
        int o = idx / 96, u = idx - o*96;
        Bs[0][o][u] = E[o*96 + u];
    }
    __syncthreads();

    float rr[2], ri[2], re[6];
    for (int c = 0; c < 16; c++){
        int cur = c & 1;
        if (c < 15){
            int oc = (c+1)*16;
            #pragma unroll
            for (int p = 0; p < 2; p++){
                int idx = t + p*256;
                int o = idx >> 5, k = idx & 31;
                rr[p] = wrp[(oc+o)*32 + k];
                ri[p] = wip[(oc+o)*32 + k];
            }
            #pragma unroll
            for (int p = 0; p < 6; p++){
                int idx = t + p*256;
                int o = idx / 96, u = idx - o*96;
                re[p] = E[(oc+o)*96 + u];
            }
        }
        #pragma unroll
        for (int o = 0; o < 16; o++){
            float4 av = *(const float4*)&As[cur][o][a*4];
            float2 b0 = *(const float2*)&Bs[cur][o][b*6];
            float2 b1 = *(const float2*)&Bs[cur][o][b*6+2];
            float2 b2 = *(const float2*)&Bs[cur][o][b*6+4];
            float a4[4] = {av.x, av.y, av.z, av.w};
            float b6[6] = {b0.x, b0.y, b1.x, b1.y, b2.x, b2.y};
            #pragma unroll
            for (int q = 0; q < 4; q++)
                #pragma unroll
                for (int w = 0; w < 6; w++)
                    acc[q*6+w] += a4[q]*b6[w];
        }
        if (c < 15){
            int nxt = cur ^ 1;
            #pragma unroll
            for (int p = 0; p < 2; p++){
                int idx = t + p*256;
                int o = idx >> 5, k = idx & 31;
                As[nxt][o][2*k]   = rr[p];
                As[nxt][o][2*k+1] = ri[p];
            }
            #pragma unroll
            for (int p = 0; p < 6; p++){
                int idx = t + p*256;
                int o = idx / 96, u = idx - o*96;
                Bs[nxt][o][u] = re[p];
            }
        }
        __syncthreads();
    }
    float invT = 1.f/(float)T;
    float* out = g_WE[s] + (size_t)i*NDIM;
    #pragma unroll
    for (int q = 0; q < 4; q++){
        int kc = a*4 + q;
        int k = kc >> 1;
        float mag = (k == 0) ? invT : 2.f*invT;
        #pragma unroll
        for (int w = 0; w < 6; w++)
            out[kc*96 + b*6 + w] = acc[q*6+w]*mag;
    }
}

// ---------------- 6. C = K @ WE  (per-scale, double-buffered) ----------------
__global__ void cgemm_kernel(){
    int colt = blockIdx.x;          // 0..95
    int rowt = blockIdx.y;          // 0..10
    int s = c_tile_s[rowt], row0 = c_tile_r[rowt];
    int Ts = seg_T(s), seg = seg_off(s);
    int col0 = colt*64;
    const float* A = &g_K[s][0][0];
    const float* B = g_WE[s];
    __shared__ float As[2][16][68];
    __shared__ float Bs[2][16][68];
    int t = threadIdx.x;
    int tm4 = (t >> 4) * 4;
    int tn4 = (t & 15) * 4;
    float acc[16];
    #pragma unroll
    for (int q = 0; q < 16; q++) acc[q] = 0.f;

    #pragma unroll
    for (int p = 0; p < 4; p++){
        int idx = t + p*256;
        int kk = idx & 15, m = idx >> 4;
        As[0][kk][m] = (row0 + m < Ts) ? A[(size_t)(row0+m)*256 + kk] : 0.f;
    }
    #pragma unroll
    for (int p = 0; p < 4; p++){
        int idx = t + p*256;
        int j = idx & 63, kk = idx >> 6;
        Bs[0][kk][j] = B[(size_t)kk*NDIM + col0 + j];
    }
    __syncthreads();

    float ra[4], rb[4];
    for (int c = 0; c < 16; c++){
        int cur = c & 1;
        if (c < 15){
            int kc = (c+1)*16;
            #pragma unroll
            for (int p = 0; p < 4; p++){
                int idx = t + p*256;
                int kk = idx & 15, m = idx >> 4;
                ra[p] = (row0 + m < Ts) ? A[(size_t)(row0+m)*256 + kc + kk] : 0.f;
            }
            #pragma unroll
            for (int p = 0; p < 4; p++){
                int idx = t + p*256;
                int j = idx & 63, kk = idx >> 6;
                rb[p] = B[(size_t)(kc+kk)*NDIM + col0 + j];
            }
        }
        #pragma unroll
        for (int kk = 0; kk < 16; kk++){
            float4 av = *(const float4*)&As[cur][kk][tm4];
            float4 bv = *(const float4*)&Bs[cur][kk][tn4];
            float a4[4] = {av.x, av.y, av.z, av.w};
            float b4[4] = {bv.x, bv.y, bv.z, bv.w};
            #pragma unroll
            for (int a = 0; a < 4; a++)
                #pragma unroll
                for (int b = 0; b < 4; b++)
                    acc[a*4+b] += a4[a]*b4[b];
        }
        if (c < 15){
            int nxt = cur ^ 1;
            #pragma unroll
            for (int p = 0; p < 4; p++){
                int idx = t + p*256;
                As[nxt][idx & 15][idx >> 4] = ra[p];
            }
            #pragma unroll
            for (int p = 0; p < 4; p++){
                int idx = t + p*256;
                Bs[nxt][idx >> 6][idx & 63] = rb[p];
            }
        }
        __syncthreads();
    }
    #pragma unroll
    for (int a = 0; a < 4; a++){
        int row = row0 + tm4 + a;
        if (row < Ts){
            float4 v = make_float4(acc[a*4+0], acc[a*4+1], acc[a*4+2], acc[a*4+3]);
            *(float4*)&g_C[(size_t)(seg+row)*NDIM + col0 + tn4] = v;
        }
    }
}

// ---------------- 7. prefix-sum chain with twiddles ----------------
// Pfx_k[d,u] = sum_{d'<=d} e^{-iw_k d'} Cc[d',k,u]
// Mpart[s*32+k][383-d][u] = Re( e^{+iw_k(d+m0)} * Pfx )
__global__ void chain_kernel(){
    int k = blockIdx.x;             // 0..31
    int s = blockIdx.y;             // 0..2
    int T = seg_T(s), seg = seg_off(s);
    int u = threadIdx.x;            // 0..95
    __shared__ float2 tw[384];
    for (int m = u; m < T; m += 96){
        float sv, cv;
        sincosf(6.28318530717958647692f*(float)m/(float)T, &sv, &cv);
        tw[m] = make_float2(cv, sv);
    }
    __syncthreads();
    int m0 = ((96 - T) % T + T) % T;
    int p1 = 0;
    int p2 = (int)(((long long)k * (long long)m0) % (long long)T);
    float Pr = 0.f, Pi = 0.f;
    const float* Cb = g_C + (size_t)seg*NDIM + (2*k)*96 + u;
    float* Mp = g_Mpart[s*32+k] + u;
    for (int d = 0; d < T; d++){
        float Cr = Cb[(size_t)d*NDIM];
        float Ci = Cb[(size_t)d*NDIM + 96];
        float2 t1 = tw[p1];
        Pr += Cr*t1.x + Ci*t1.y;
        Pi += Ci*t1.x - Cr*t1.y;
        float2 t2 = tw[p2];
        Mp[(size_t)(383-d)*96] = t2.x*Pr - t2.y*Pi;
        p1 += k; if (p1 >= T) p1 -= T;
        p2 += k; if (p2 >= T) p2 -= T;
    }
}

// ---------------- 8. reduce Mpart over (s,k) with validity ranges ----------
__global__ void mreduce_kernel(){
    int idx = blockIdx.x*256 + threadIdx.x;   // 0..36863
    if (idx >= 384*96) return;
    int g = idx / 96;
    float a = 0.f;
    #pragma unroll 8
    for (int p = 64; p < 96; p++) a += g_Mpart[p][idx];   // s2: all g
    if (g >= 192){
        #pragma unroll 8
        for (int p = 32; p < 64; p++) a += g_Mpart[p][idx];
    }
    if (g >= 288){
        #pragma unroll 8
        for (int p = 0; p < 32; p++) a += g_Mpart[p][idx];
    }
    g_M[idx] = a;
}

__global__ void msum_kernel(){
    int u = threadIdx.x;  // 96
    float a = 0.f;
    for (int g = 0; g < 384; g++) a += g_M[g*96 + u];
    g_Msum[u] = a;
}

// ---------------- 9. final ----------------
__global__ void final_kernel(const float* __restrict__ x,
                             const float* __restrict__ mlp_b,
                             float* __restrict__ out){
    int b = blockIdx.x, u = blockIdx.y;
    int e = threadIdx.x;   // 64
    __shared__ float msh[384];
    for (int g = e; g < 384; g += 64) msh[g] = g_M[g*96 + u];
    __syncthreads();
    const float* xp = x + ((size_t)b*LSEQ + 336)*ECH + e;
    float acc = 0.f;
    #pragma unroll 8
    for (int g = 0; g < 384; g++) acc += xp[(size_t)g*ECH] * msh[g];
    float mean = g_mean[b*ECH+e], sd = g_std[b*ECH+e];
    out[((size_t)b*OUTL + u)*ECH + e] = acc + mean*(1.f - g_Msum[u]) + mlp_b[0]*sd;
}

// ---------------- launch ----------------
extern "C" void kernel_launch(void* const* d_in, const int* in_sizes, int n_in,
                              void* d_out, int out_size){
    const float* x     = (const float*)d_in[0];
    const float* wr    = (const float*)d_in[1];
    const float* wi    = (const float*)d_in[2];
    const float* mlp_w = (const float*)d_in[3];
    const float* mlp_b = (const float*)d_in[4];
    const float* A     = (const float*)d_in[5];
    const float* Bv    = (const float*)d_in[6];
    const float* ev    = (const float*)d_in[7];
    float* out = (float*)d_out;

    stats_kernel<<<BATCH, 256>>>(x);
    egen_kernel<<<3, 256>>>(ev, mlp_w);
    init_kernel<<<(3*65536 + 768 + 255)/256, 256>>>(A, Bv);
    wegemm_kernel<<<dim3(256,3), 256>>>(wr, wi);
    for (int r = 0; r < 9; r++){
        rgemm_kernel<<<dim3(16,3,8), 256>>>(r);
        rred_kernel<<<dim3(64,3,2), 256>>>(r);
    }
    cgemm_kernel<<<dim3(96,11), 256>>>();
    chain_kernel<<<dim3(32,3), 96>>>();
    mreduce_kernel<<<144, 256>>>();
    msum_kernel<<<1, 96>>>();
    final_kernel<<<dim3(BATCH, OUTL), 64>>>(x, mlp_b, out);
}